// round 3
// baseline (speedup 1.0000x reference)
#include <cuda_runtime.h>
#include <cuda_bf16.h>

// HybridQuanvolutionFraudNet — reference ends with log_softmax over a
// singleton axis ([B,1]), which is identically zero for every element,
// independent of all inputs. Exact output: zeros([2048,1], float32).
//
// We are at the one-node CUDA-graph replay floor (~3.3us kernel, all pipes
// ~0%): R1 (grid=8, scalar STG) and R2 (grid=1, STG.128) timed identically.
// This round strips the last ALU: no size param, no predicate — 512 threads,
// one unconditional STG.E.128 each (8192 B = 2048 floats).

__global__ void __launch_bounds__(512, 1)
HybridQuanvolutionFraudNet_65481071399590_kernel(float4* __restrict__ out) {
    out[threadIdx.x] = make_float4(0.f, 0.f, 0.f, 0.f);
}

// Defensive fallback for any other out_size (not expected for this problem).
__global__ void HybridQuanvolutionFraudNet_65481071399590_zero_any(float* __restrict__ out, int n) {
    int i = blockIdx.x * blockDim.x + threadIdx.x;
    if (i < n) out[i] = 0.0f;
}

extern "C" void kernel_launch(void* const* d_in, const int* in_sizes, int n_in,
                              void* d_out, int out_size) {
    (void)d_in; (void)in_sizes; (void)n_in;
    if (out_size == 2048) {
        HybridQuanvolutionFraudNet_65481071399590_kernel<<<1, 512>>>((float4*)d_out);
    } else {
        int threads = 256;
        int blocks = (out_size + threads - 1) / threads;
        HybridQuanvolutionFraudNet_65481071399590_zero_any<<<blocks, threads>>>((float*)d_out, out_size);
    }
}

// round 4
// speedup vs baseline: 1.1513x; 1.1513x over previous
#include <cuda_runtime.h>
#include <cuda_bf16.h>

// HybridQuanvolutionFraudNet — reference ends with log_softmax over a
// singleton axis ([B,1]): identically zero for every element, independent of
// all inputs. The quanvolution + MLP pipeline is algebraically dead code.
// Exact output: zeros([2048,1], float32). rel_err = 0 on any seed.
//
// Perf status: at the one-node CUDA-graph replay floor. Three structurally
// different kernels (grid=8 scalar STG; grid=1 predicated STG.128; grid=1
// unconditional STG.128) all measure 3.30-3.42 us kernel time with every pipe
// at ~0% — the time is fixed launch+drain cost, not the body. Bench-level
// dur_us jitters +-1 us around ~4.6. This is the terminal kernel.

__global__ void __launch_bounds__(512, 1)
HybridQuanvolutionFraudNet_65481071399590_kernel(float4* __restrict__ out) {
    out[threadIdx.x] = make_float4(0.f, 0.f, 0.f, 0.f);  // 512 x STG.E.128 = 8192 B
}

// Defensive fallback for any other out_size (not expected for this problem).
__global__ void HybridQuanvolutionFraudNet_65481071399590_zero_any(float* __restrict__ out, int n) {
    int i = blockIdx.x * blockDim.x + threadIdx.x;
    if (i < n) out[i] = 0.0f;
}

extern "C" void kernel_launch(void* const* d_in, const int* in_sizes, int n_in,
                              void* d_out, int out_size) {
    (void)d_in; (void)in_sizes; (void)n_in;
    if (out_size == 2048) {
        HybridQuanvolutionFraudNet_65481071399590_kernel<<<1, 512>>>((float4*)d_out);
    } else {
        int threads = 256;
        int blocks = (out_size + threads - 1) / threads;
        HybridQuanvolutionFraudNet_65481071399590_zero_any<<<blocks, threads>>>((float*)d_out, out_size);
    }
}